// round 1
// baseline (speedup 1.0000x reference)
#include <cuda_runtime.h>
#include <cstdint>

#define FDIM   128
#define MTOT   16
#define KDIM   132          // F + NL
#define KP     136          // padded K (mult of 8)
#define NP     136          // padded N (mult of 8)
#define ROWS   256          // rows per CTA tile
#define THREADS 256
#define NT     17           // 136/8 tiles in both N and K

// smem float offsets
#define W_OFF  0
#define Y_OFF  (KP*NP)                 // 18496
#define H_OFF  (Y_OFF + ROWS*KP)       // +34816 = 53312
#define B_OFF  (H_OFF + ROWS*4)        // +1024  = 54336
#define SMEM_FLOATS (B_OFF + NP)       // 54472
#define SMEM_BYTES  (SMEM_FLOATS * 4)  // 217888

__device__ __forceinline__ uint32_t f2tf32(float v) {
    uint32_t u;
    asm("cvt.rna.tf32.f32 %0, %1;" : "=r"(u) : "f"(v));
    return u;
}

#define MMA(C, A, B0, B1)                                                          \
    asm volatile(                                                                  \
        "mma.sync.aligned.m16n8k8.row.col.f32.tf32.tf32.f32 "                      \
        "{%0,%1,%2,%3},{%4,%5,%6,%7},{%8,%9},{%0,%1,%2,%3};"                       \
        : "+f"((C)[0]), "+f"((C)[1]), "+f"((C)[2]), "+f"((C)[3])                   \
        : "r"((A)[0]), "r"((A)[1]), "r"((A)[2]), "r"((A)[3]), "r"(B0), "r"(B1))

__global__ __launch_bounds__(THREADS, 1)
void ib_kernel(const float* __restrict__ x,
               const float* __restrict__ chi,
               const float* __restrict__ W,
               const float* __restrict__ b,
               float* __restrict__ out_a,
               float* __restrict__ out_chi,
               int n, int ntiles)
{
    extern __shared__ float sm[];
    float* Wsm = sm + W_OFF;   // [KP][NP]
    float* ysm = sm + Y_OFF;   // [ROWS][KP]
    float* hsm = sm + H_OFF;   // [ROWS][4]
    float* bsm = sm + B_OFF;   // [NP]

    const int tid  = threadIdx.x;
    const int warp = tid >> 5;
    const int lane = tid & 31;
    const int g = lane >> 2;   // 0..7
    const int q = lane & 3;    // 0..3
    const int rb = warp * 32;  // warp's row base within tile

    // ---- load W (once per CTA), zero-padded to 136x136 ----
    for (int i = tid; i < KP * NP; i += THREADS) Wsm[i] = 0.0f;
    __syncthreads();
    for (int i = tid; i < KDIM * KDIM; i += THREADS) {
        int k = i / KDIM, j = i % KDIM;
        Wsm[k * NP + j] = W[i];
    }
    if (tid < NP) bsm[tid] = (tid < KDIM) ? b[tid] : 0.0f;
    __syncthreads();

    for (int tile = blockIdx.x; tile < ntiles; tile += gridDim.x) {
        const long long row0 = (long long)tile * ROWS;

        // ---- fill y tile: x part (vectorized, coalesced) ----
        #pragma unroll
        for (int it = 0; it < (ROWS * FDIM) / (THREADS * 4); ++it) {
            int linear = (it * THREADS + tid) * 4;
            int r = linear >> 7;        // /128
            int c = linear & 127;
            long long gr = row0 + r;
            float4 v = make_float4(0.f, 0.f, 0.f, 0.f);
            if (gr < n) v = *(const float4*)(x + gr * FDIM + c);
            *(float4*)(ysm + r * KP + c) = v;
        }
        // ---- fill y tile: d_chi part (thread t -> row t) ----
        {
            int r = tid;
            long long gr = row0 + r;
            float s0 = 0.f, s1 = 0.f, s2 = 0.f, s3 = 0.f;
            if (gr < n) {
                const float4* cp = (const float4*)(chi + gr * MTOT);
                float4 c0 = cp[0], c1 = cp[1], c2 = cp[2], c3 = cp[3];
                s0 = c0.x * c0.x;
                s1 = c0.y * c0.y + c0.z * c0.z + c0.w * c0.w;
                s2 = c1.x * c1.x + c1.y * c1.y + c1.z * c1.z + c1.w * c1.w
                   + c2.x * c2.x;
                s3 = c2.y * c2.y + c2.z * c2.z + c2.w * c2.w
                   + c3.x * c3.x + c3.y * c3.y + c3.z * c3.z + c3.w * c3.w;
            }
            float* yr = ysm + r * KP;
            yr[128] = s0; yr[129] = s1; yr[130] = s2; yr[131] = s3;
            yr[132] = 0.f; yr[133] = 0.f; yr[134] = 0.f; yr[135] = 0.f;
        }
        __syncthreads();

        // ---- accumulators, bias-initialized ----
        float acc[2][NT][4];
        #pragma unroll
        for (int n0 = 0; n0 < NT; n0++) {
            float b0 = bsm[n0 * 8 + 2 * q];
            float b1v = bsm[n0 * 8 + 2 * q + 1];
            #pragma unroll
            for (int mt = 0; mt < 2; mt++) {
                acc[mt][n0][0] = b0;  acc[mt][n0][1] = b1v;
                acc[mt][n0][2] = b0;  acc[mt][n0][3] = b1v;
            }
        }

        // ---- mainloop: K in 17 steps of 8, 3xTF32 compensated ----
        #pragma unroll 1
        for (int k0 = 0; k0 < NT; k0++) {
            const int kk = k0 * 8;
            uint32_t ahi[2][4], alo[2][4];
            #pragma unroll
            for (int mt = 0; mt < 2; mt++) {
                int r = rb + mt * 16;
                float a0 = ysm[(r + g) * KP + kk + q];
                float a1 = ysm[(r + g + 8) * KP + kk + q];
                float a2 = ysm[(r + g) * KP + kk + q + 4];
                float a3 = ysm[(r + g + 8) * KP + kk + q + 4];
                ahi[mt][0] = f2tf32(a0);
                ahi[mt][1] = f2tf32(a1);
                ahi[mt][2] = f2tf32(a2);
                ahi[mt][3] = f2tf32(a3);
                alo[mt][0] = f2tf32(a0 - __uint_as_float(ahi[mt][0]));
                alo[mt][1] = f2tf32(a1 - __uint_as_float(ahi[mt][1]));
                alo[mt][2] = f2tf32(a2 - __uint_as_float(ahi[mt][2]));
                alo[mt][3] = f2tf32(a3 - __uint_as_float(ahi[mt][3]));
            }
            #pragma unroll
            for (int n0 = 0; n0 < NT; n0++) {
                int ncol = n0 * 8 + g;
                float w0 = Wsm[(kk + q) * NP + ncol];
                float w1 = Wsm[(kk + q + 4) * NP + ncol];
                uint32_t bh0 = f2tf32(w0);
                uint32_t bh1 = f2tf32(w1);
                uint32_t bl0 = f2tf32(w0 - __uint_as_float(bh0));
                uint32_t bl1 = f2tf32(w1 - __uint_as_float(bh1));
                #pragma unroll
                for (int mt = 0; mt < 2; mt++) {
                    MMA(acc[mt][n0], ahi[mt], bh0, bh1);
                    MMA(acc[mt][n0], alo[mt], bh0, bh1);
                    MMA(acc[mt][n0], ahi[mt], bl0, bl1);
                }
            }
        }

        // ---- epilogue: write a1 (cols <128) + stage b1 cols (128..131) ----
        #pragma unroll
        for (int mt = 0; mt < 2; mt++) {
            #pragma unroll
            for (int n0 = 0; n0 < NT; n0++) {
                int col = n0 * 8 + 2 * q;
                int rl0 = rb + mt * 16 + g;
                int rl1 = rl0 + 8;
                float v0 = acc[mt][n0][0], v1 = acc[mt][n0][1];
                float v2 = acc[mt][n0][2], v3 = acc[mt][n0][3];
                if (col < FDIM) {
                    long long gr0 = row0 + rl0;
                    long long gr1 = row0 + rl1;
                    if (gr0 < n) *(float2*)(out_a + gr0 * FDIM + col) = make_float2(v0, v1);
                    if (gr1 < n) *(float2*)(out_a + gr1 * FDIM + col) = make_float2(v2, v3);
                } else if (col < FDIM + 4) {   // col == 128 (q=0) or 130 (q=1)
                    int cc = col - FDIM;
                    hsm[rl0 * 4 + cc]     = v0;
                    hsm[rl0 * 4 + cc + 1] = v1;
                    hsm[rl1 * 4 + cc]     = v2;
                    hsm[rl1 * 4 + cc + 1] = v3;
                }
            }
        }
        __syncthreads();

        // ---- chi_out = b1[:, seg] * chi ----
        {
            int r = tid;
            long long gr = row0 + r;
            if (gr < n) {
                float h0 = hsm[r * 4 + 0], h1 = hsm[r * 4 + 1];
                float h2 = hsm[r * 4 + 2], h3 = hsm[r * 4 + 3];
                const float4* cp = (const float4*)(chi + gr * MTOT);
                float4 c0 = cp[0], c1 = cp[1], c2 = cp[2], c3 = cp[3];
                float4 o0 = make_float4(h0 * c0.x, h1 * c0.y, h1 * c0.z, h1 * c0.w);
                float4 o1 = make_float4(h2 * c1.x, h2 * c1.y, h2 * c1.z, h2 * c1.w);
                float4 o2 = make_float4(h2 * c2.x, h3 * c2.y, h3 * c2.z, h3 * c2.w);
                float4 o3 = make_float4(h3 * c3.x, h3 * c3.y, h3 * c3.z, h3 * c3.w);
                float4* op = (float4*)(out_chi + gr * MTOT);
                op[0] = o0; op[1] = o1; op[2] = o2; op[3] = o3;
            }
        }
        __syncthreads();   // protects ysm/hsm before next tile's fill
    }
}

extern "C" void kernel_launch(void* const* d_in, const int* in_sizes, int n_in,
                              void* d_out, int out_size)
{
    const float* x   = (const float*)d_in[0];
    const float* chi = (const float*)d_in[1];
    // d_in[2] = point_mask (unused by reference math)
    const float* W   = (const float*)d_in[3];
    const float* b   = (const float*)d_in[4];

    int n = in_sizes[0] / FDIM;
    float* out_a   = (float*)d_out;
    float* out_chi = out_a + (size_t)n * FDIM;

    int ntiles = (n + ROWS - 1) / ROWS;

    int dev = 0;
    cudaGetDevice(&dev);
    int smcount = 148;
    cudaDeviceGetAttribute(&smcount, cudaDevAttrMultiProcessorCount, dev);

    cudaFuncSetAttribute(ib_kernel, cudaFuncAttributeMaxDynamicSharedMemorySize,
                         SMEM_BYTES);

    int grid = ntiles < smcount ? ntiles : smcount;
    ib_kernel<<<grid, THREADS, SMEM_BYTES>>>(x, chi, W, b, out_a, out_chi, n, ntiles);
}

// round 2
// speedup vs baseline: 1.7534x; 1.7534x over previous
#include <cuda_runtime.h>
#include <cuda_fp16.h>
#include <cstdint>

#define FDIM   128
#define MTOT   16
#define KDIM   132
#define KP     136          // padded K extent in smem (halves)
#define ROWS   256
#define THREADS 512

// dynamic smem byte offsets
#define WHI_OFF 0
#define WLO_OFF (WHI_OFF + KP*KP*2)       // 36992
#define YHI_OFF (WLO_OFF + KP*KP*2)       // 73984
#define YLO_OFF (YHI_OFF + ROWS*KP*2)     // 143616
#define HSM_OFF (YLO_OFF + ROWS*KP*2)     // 213248
#define BSM_OFF (HSM_OFF + ROWS*4*4)      // 217344
#define SMEM_BYTES (BSM_OFF + KP*4)       // 217888

__device__ __forceinline__ uint32_t ldu32(const __half* p) {
    return *reinterpret_cast<const uint32_t*>(p);
}

#define MMA16(C, A, B0, B1)                                                    \
    asm volatile(                                                              \
        "mma.sync.aligned.m16n8k16.row.col.f32.f16.f16.f32 "                   \
        "{%0,%1,%2,%3},{%4,%5,%6,%7},{%8,%9},{%0,%1,%2,%3};"                   \
        : "+f"((C)[0]), "+f"((C)[1]), "+f"((C)[2]), "+f"((C)[3])               \
        : "r"((A)[0]), "r"((A)[1]), "r"((A)[2]), "r"((A)[3]), "r"(B0), "r"(B1))

#define MMA8(C, A0, A1, B0)                                                    \
    asm volatile(                                                              \
        "mma.sync.aligned.m16n8k8.row.col.f32.f16.f16.f32 "                    \
        "{%0,%1,%2,%3},{%4,%5},{%6},{%0,%1,%2,%3};"                            \
        : "+f"((C)[0]), "+f"((C)[1]), "+f"((C)[2]), "+f"((C)[3])               \
        : "r"((A0)), "r"((A1)), "r"(B0))

// One warp computes rows [rb, rb+32) x n-tiles [NBASE, NBASE+NT)
template<int NT, int NBASE>
__device__ __forceinline__ void tile_compute(
    const __half* __restrict__ yhi, const __half* __restrict__ ylo,
    const __half* __restrict__ whi, const __half* __restrict__ wlo,
    const float* __restrict__ bsm, float* __restrict__ hsm,
    float* __restrict__ out_a, long long row0, int n,
    int rb, int g, int q)
{
    float acc[2][NT][4];
    #pragma unroll
    for (int n0 = 0; n0 < NT; n0++) {
        int col = (NBASE + n0) * 8 + 2 * q;
        float b0 = bsm[col], b1 = bsm[col + 1];
        #pragma unroll
        for (int mt = 0; mt < 2; mt++) {
            acc[mt][n0][0] = b0; acc[mt][n0][1] = b1;
            acc[mt][n0][2] = b0; acc[mt][n0][3] = b1;
        }
    }

    // ---- 8 full k16 chunks ----
    #pragma unroll 1
    for (int k0 = 0; k0 < 8; k0++) {
        const int kk = k0 * 16;
        uint32_t ahi[2][4], alo[2][4];
        #pragma unroll
        for (int mt = 0; mt < 2; mt++) {
            int r0 = rb + mt * 16 + g;
            int r1 = r0 + 8;
            int kq  = kk + q * 2;
            ahi[mt][0] = ldu32(yhi + r0 * KP + kq);
            ahi[mt][1] = ldu32(yhi + r1 * KP + kq);
            ahi[mt][2] = ldu32(yhi + r0 * KP + kq + 8);
            ahi[mt][3] = ldu32(yhi + r1 * KP + kq + 8);
            alo[mt][0] = ldu32(ylo + r0 * KP + kq);
            alo[mt][1] = ldu32(ylo + r1 * KP + kq);
            alo[mt][2] = ldu32(ylo + r0 * KP + kq + 8);
            alo[mt][3] = ldu32(ylo + r1 * KP + kq + 8);
        }
        #pragma unroll
        for (int n0 = 0; n0 < NT; n0++) {
            int cr = ((NBASE + n0) * 8 + g) * KP + kk + q * 2;
            uint32_t bh0 = ldu32(whi + cr);
            uint32_t bh1 = ldu32(whi + cr + 8);
            uint32_t bl0 = ldu32(wlo + cr);
            uint32_t bl1 = ldu32(wlo + cr + 8);
            #pragma unroll
            for (int mt = 0; mt < 2; mt++) {
                MMA16(acc[mt][n0], ahi[mt], bh0, bh1);
                MMA16(acc[mt][n0], alo[mt], bh0, bh1);
                MMA16(acc[mt][n0], ahi[mt], bl0, bl1);
            }
        }
    }

    // ---- tail k8 chunk (k = 128..135, real data 128..131) ----
    {
        const int kk = 128;
        uint32_t ahi[2][2], alo[2][2];
        #pragma unroll
        for (int mt = 0; mt < 2; mt++) {
            int r0 = rb + mt * 16 + g;
            int r1 = r0 + 8;
            int kq = kk + q * 2;
            ahi[mt][0] = ldu32(yhi + r0 * KP + kq);
            ahi[mt][1] = ldu32(yhi + r1 * KP + kq);
            alo[mt][0] = ldu32(ylo + r0 * KP + kq);
            alo[mt][1] = ldu32(ylo + r1 * KP + kq);
        }
        #pragma unroll
        for (int n0 = 0; n0 < NT; n0++) {
            int cr = ((NBASE + n0) * 8 + g) * KP + kk + q * 2;
            uint32_t bh0 = ldu32(whi + cr);
            uint32_t bl0 = ldu32(wlo + cr);
            #pragma unroll
            for (int mt = 0; mt < 2; mt++) {
                MMA8(acc[mt][n0], ahi[mt][0], ahi[mt][1], bh0);
                MMA8(acc[mt][n0], alo[mt][0], alo[mt][1], bh0);
                MMA8(acc[mt][n0], ahi[mt][0], ahi[mt][1], bl0);
            }
        }
    }

    // ---- epilogue: a1 (cols < 128) to gmem, b1 (cols 128..131) to hsm ----
    #pragma unroll
    for (int mt = 0; mt < 2; mt++) {
        #pragma unroll
        for (int n0 = 0; n0 < NT; n0++) {
            int col = (NBASE + n0) * 8 + 2 * q;
            int rl0 = rb + mt * 16 + g;
            int rl1 = rl0 + 8;
            float v0 = acc[mt][n0][0], v1 = acc[mt][n0][1];
            float v2 = acc[mt][n0][2], v3 = acc[mt][n0][3];
            if (col < FDIM) {
                long long gr0 = row0 + rl0;
                long long gr1 = row0 + rl1;
                if (gr0 < n) *(float2*)(out_a + gr0 * FDIM + col) = make_float2(v0, v1);
                if (gr1 < n) *(float2*)(out_a + gr1 * FDIM + col) = make_float2(v2, v3);
            } else if (col < FDIM + 4) {
                int cc = col - FDIM;
                hsm[rl0 * 4 + cc]     = v0;
                hsm[rl0 * 4 + cc + 1] = v1;
                hsm[rl1 * 4 + cc]     = v2;
                hsm[rl1 * 4 + cc + 1] = v3;
            }
        }
    }
}

__global__ __launch_bounds__(THREADS, 1)
void ib_kernel(const float* __restrict__ x,
               const float* __restrict__ chi,
               const float* __restrict__ W,
               const float* __restrict__ b,
               float* __restrict__ out_a,
               float* __restrict__ out_chi,
               int n, int ntiles)
{
    extern __shared__ char smraw[];
    __half* whi = (__half*)(smraw + WHI_OFF);   // [KP n][KP k]  (W transposed)
    __half* wlo = (__half*)(smraw + WLO_OFF);
    __half* yhi = (__half*)(smraw + YHI_OFF);   // [ROWS][KP]
    __half* ylo = (__half*)(smraw + YLO_OFF);
    float*  hsm = (float*) (smraw + HSM_OFF);   // [ROWS][4]
    float*  bsm = (float*) (smraw + BSM_OFF);   // [KP]

    const int tid  = threadIdx.x;
    const int warp = tid >> 5;
    const int lane = tid & 31;
    const int g = lane >> 2;
    const int q = lane & 3;
    const int rb = (warp & 7) * 32;   // row base within tile
    const int wn = warp >> 3;         // 0: n-tiles 0..8, 1: n-tiles 9..16

    // ---- load + split W once (transposed), zero-padded ----
    for (int i = tid; i < KP * KP; i += THREADS) { whi[i] = __float2half(0.f); wlo[i] = __float2half(0.f); }
    __syncthreads();
    for (int i = tid; i < KDIM * KDIM; i += THREADS) {
        int k = i / KDIM, j = i % KDIM;
        float v = W[i];
        __half h = __float2half_rn(v);
        __half l = __float2half_rn(v - __half2float(h));
        whi[j * KP + k] = h;
        wlo[j * KP + k] = l;
    }
    if (tid < KP) bsm[tid] = (tid < KDIM) ? b[tid] : 0.0f;
    __syncthreads();

    for (int tile = blockIdx.x; tile < ntiles; tile += gridDim.x) {
        const long long row0 = (long long)tile * ROWS;

        // ---- fill y tile: x part, split to hi/lo halves ----
        #pragma unroll
        for (int it = 0; it < (ROWS * FDIM) / (THREADS * 4); ++it) {
            int linear = (it * THREADS + tid) * 4;
            int r = linear >> 7;
            int c = linear & 127;
            long long gr = row0 + r;
            float4 v = make_float4(0.f, 0.f, 0.f, 0.f);
            if (gr < n) v = *(const float4*)(x + gr * FDIM + c);
            __half h0 = __float2half_rn(v.x), h1 = __float2half_rn(v.y);
            __half h2 = __float2half_rn(v.z), h3 = __float2half_rn(v.w);
            __half l0 = __float2half_rn(v.x - __half2float(h0));
            __half l1 = __float2half_rn(v.y - __half2float(h1));
            __half l2 = __float2half_rn(v.z - __half2float(h2));
            __half l3 = __float2half_rn(v.w - __half2float(h3));
            *(__half2*)(yhi + r * KP + c)     = __halves2half2(h0, h1);
            *(__half2*)(yhi + r * KP + c + 2) = __halves2half2(h2, h3);
            *(__half2*)(ylo + r * KP + c)     = __halves2half2(l0, l1);
            *(__half2*)(ylo + r * KP + c + 2) = __halves2half2(l2, l3);
        }
        // ---- fill y tile: d_chi columns 128..131 (+ zero pad to 135) ----
        if (tid < ROWS) {
            int r = tid;
            long long gr = row0 + r;
            float s0 = 0.f, s1 = 0.f, s2 = 0.f, s3 = 0.f;
            if (gr < n) {
                const float4* cp = (const float4*)(chi + gr * MTOT);
                float4 c0 = cp[0], c1 = cp[1], c2 = cp[2], c3 = cp[3];
                s0 = c0.x * c0.x;
                s1 = c0.y * c0.y + c0.z * c0.z + c0.w * c0.w;
                s2 = c1.x * c1.x + c1.y * c1.y + c1.z * c1.z + c1.w * c1.w
                   + c2.x * c2.x;
                s3 = c2.y * c2.y + c2.z * c2.z + c2.w * c2.w
                   + c3.x * c3.x + c3.y * c3.y + c3.z * c3.z + c3.w * c3.w;
            }
            __half h0 = __float2half_rn(s0), h1 = __float2half_rn(s1);
            __half h2 = __float2half_rn(s2), h3 = __float2half_rn(s3);
            __half l0 = __float2half_rn(s0 - __half2float(h0));
            __half l1 = __float2half_rn(s1 - __half2float(h1));
            __half l2 = __float2half_rn(s2 - __half2float(h2));
            __half l3 = __float2half_rn(s3 - __half2float(h3));
            __half z  = __float2half(0.f);
            __half* yh = yhi + r * KP + 128;
            __half* yl = ylo + r * KP + 128;
            *(__half2*)(yh)     = __halves2half2(h0, h1);
            *(__half2*)(yh + 2) = __halves2half2(h2, h3);
            *(__half2*)(yh + 4) = __halves2half2(z, z);
            *(__half2*)(yh + 6) = __halves2half2(z, z);
            *(__half2*)(yl)     = __halves2half2(l0, l1);
            *(__half2*)(yl + 2) = __halves2half2(l2, l3);
            *(__half2*)(yl + 4) = __halves2half2(z, z);
            *(__half2*)(yl + 6) = __halves2half2(z, z);
        }
        __syncthreads();

        // ---- GEMM + a1/b1 epilogue ----
        if (wn == 0)
            tile_compute<9, 0>(yhi, ylo, whi, wlo, bsm, hsm, out_a, row0, n, rb, g, q);
        else
            tile_compute<8, 9>(yhi, ylo, whi, wlo, bsm, hsm, out_a, row0, n, rb, g, q);
        __syncthreads();

        // ---- chi_out = b1[:, seg] * chi : 2 threads per row ----
        {
            int r = tid >> 1;
            int half_idx = tid & 1;
            long long gr = row0 + r;
            if (gr < n) {
                float h0 = hsm[r * 4 + 0], h1 = hsm[r * 4 + 1];
                float h2 = hsm[r * 4 + 2], h3 = hsm[r * 4 + 3];
                const float4* cp = (const float4*)(chi + gr * MTOT);
                float4* op = (float4*)(out_chi + gr * MTOT);
                if (half_idx == 0) {
                    float4 c0 = cp[0], c1 = cp[1];
                    op[0] = make_float4(h0 * c0.x, h1 * c0.y, h1 * c0.z, h1 * c0.w);
                    op[1] = make_float4(h2 * c1.x, h2 * c1.y, h2 * c1.z, h2 * c1.w);
                } else {
                    float4 c2 = cp[2], c3 = cp[3];
                    op[2] = make_float4(h2 * c2.x, h3 * c2.y, h3 * c2.z, h3 * c2.w);
                    op[3] = make_float4(h3 * c3.x, h3 * c3.y, h3 * c3.z, h3 * c3.w);
                }
            }
        }
        __syncthreads();
    }
}

extern "C" void kernel_launch(void* const* d_in, const int* in_sizes, int n_in,
                              void* d_out, int out_size)
{
    const float* x   = (const float*)d_in[0];
    const float* chi = (const float*)d_in[1];
    // d_in[2] = point_mask (all-ones; unused by reference math)
    const float* W   = (const float*)d_in[3];
    const float* b   = (const float*)d_in[4];

    int n = in_sizes[0] / FDIM;
    float* out_a   = (float*)d_out;
    float* out_chi = out_a + (size_t)n * FDIM;

    int ntiles = (n + ROWS - 1) / ROWS;

    int dev = 0;
    cudaGetDevice(&dev);
    int smcount = 148;
    cudaDeviceGetAttribute(&smcount, cudaDevAttrMultiProcessorCount, dev);

    cudaFuncSetAttribute(ib_kernel, cudaFuncAttributeMaxDynamicSharedMemorySize,
                         SMEM_BYTES);

    int grid = ntiles < smcount ? ntiles : smcount;
    ib_kernel<<<grid, THREADS, SMEM_BYTES>>>(x, chi, W, b, out_a, out_chi, n, ntiles);
}

// round 3
// speedup vs baseline: 1.8927x; 1.0794x over previous
#include <cuda_runtime.h>
#include <cuda_fp16.h>
#include <cstdint>

#define FDIM   128
#define MTOT   16
#define KDIM   132
#define KP     136
#define ROWS   128
#define THREADS 512

// dynamic smem byte offsets
#define WHI_OFF 0
#define WLO_OFF (KP*KP*2)                  // 36992
#define Y_OFF   (2*KP*KP*2)                // 73984
#define YBUF_BYTES (2*ROWS*KP*2)           // 69632  (hi plane + lo plane)
#define HSM_OFF (Y_OFF + 2*YBUF_BYTES)     // 213248
#define BSM_OFF (HSM_OFF + ROWS*4*4)       // 215296
#define SMEM_BYTES (BSM_OFF + KP*4)        // 215840

__device__ __forceinline__ uint32_t ldu32(const __half* p) {
    return *reinterpret_cast<const uint32_t*>(p);
}
__device__ __forceinline__ uint32_t pack2(__half a, __half b) {
    __half2 h = __halves2half2(a, b);
    return *reinterpret_cast<uint32_t*>(&h);
}

#define MMA16(C, A, B0, B1)                                                    \
    asm volatile(                                                              \
        "mma.sync.aligned.m16n8k16.row.col.f32.f16.f16.f32 "                   \
        "{%0,%1,%2,%3},{%4,%5,%6,%7},{%8,%9},{%0,%1,%2,%3};"                   \
        : "+f"((C)[0]), "+f"((C)[1]), "+f"((C)[2]), "+f"((C)[3])               \
        : "r"((A)[0]), "r"((A)[1]), "r"((A)[2]), "r"((A)[3]), "r"(B0), "r"(B1))

#define MMA8(C, A0, A1, B0)                                                    \
    asm volatile(                                                              \
        "mma.sync.aligned.m16n8k8.row.col.f32.f16.f16.f32 "                    \
        "{%0,%1,%2,%3},{%4,%5},{%6},{%0,%1,%2,%3};"                            \
        : "+f"((C)[0]), "+f"((C)[1]), "+f"((C)[2]), "+f"((C)[3])               \
        : "r"((A0)), "r"((A1)), "r"(B0))

// One warp: rows [rb, rb+32) x n-tiles [NBASE, NBASE+NT)
template<int NT, int NBASE>
__device__ __forceinline__ void tile_compute(
    const __half* __restrict__ yhi, const __half* __restrict__ ylo,
    const __half* __restrict__ whi, const __half* __restrict__ wlo,
    const float* __restrict__ bsm, float* __restrict__ hsm,
    float* __restrict__ out_a, long long row0, int n,
    int rb, int g, int q)
{
    float acc[2][NT][4];
    #pragma unroll
    for (int n0 = 0; n0 < NT; n0++) {
        int col = (NBASE + n0) * 8 + 2 * q;
        float b0 = bsm[col], b1 = bsm[col + 1];
        #pragma unroll
        for (int mt = 0; mt < 2; mt++) {
            acc[mt][n0][0] = b0; acc[mt][n0][1] = b1;
            acc[mt][n0][2] = b0; acc[mt][n0][3] = b1;
        }
    }

    #pragma unroll 1
    for (int k0 = 0; k0 < 8; k0++) {
        const int kk = k0 * 16;
        uint32_t ahi[2][4], alo[2][4];
        #pragma unroll
        for (int mt = 0; mt < 2; mt++) {
            int r0 = rb + mt * 16 + g;
            int r1 = r0 + 8;
            int kq = kk + q * 2;
            ahi[mt][0] = ldu32(yhi + r0 * KP + kq);
            ahi[mt][1] = ldu32(yhi + r1 * KP + kq);
            ahi[mt][2] = ldu32(yhi + r0 * KP + kq + 8);
            ahi[mt][3] = ldu32(yhi + r1 * KP + kq + 8);
            alo[mt][0] = ldu32(ylo + r0 * KP + kq);
            alo[mt][1] = ldu32(ylo + r1 * KP + kq);
            alo[mt][2] = ldu32(ylo + r0 * KP + kq + 8);
            alo[mt][3] = ldu32(ylo + r1 * KP + kq + 8);
        }
        #pragma unroll
        for (int n0 = 0; n0 < NT; n0++) {
            int cr = ((NBASE + n0) * 8 + g) * KP + kk + q * 2;
            uint32_t bh0 = ldu32(whi + cr);
            uint32_t bh1 = ldu32(whi + cr + 8);
            uint32_t bl0 = ldu32(wlo + cr);
            uint32_t bl1 = ldu32(wlo + cr + 8);
            #pragma unroll
            for (int mt = 0; mt < 2; mt++) {
                MMA16(acc[mt][n0], ahi[mt], bh0, bh1);
                MMA16(acc[mt][n0], alo[mt], bh0, bh1);
                MMA16(acc[mt][n0], ahi[mt], bl0, bl1);
            }
        }
    }

    // tail k8 chunk (k = 128..135; 128..131 real)
    {
        const int kk = 128;
        uint32_t ahi[2][2], alo[2][2];
        #pragma unroll
        for (int mt = 0; mt < 2; mt++) {
            int r0 = rb + mt * 16 + g;
            int r1 = r0 + 8;
            int kq = kk + q * 2;
            ahi[mt][0] = ldu32(yhi + r0 * KP + kq);
            ahi[mt][1] = ldu32(yhi + r1 * KP + kq);
            alo[mt][0] = ldu32(ylo + r0 * KP + kq);
            alo[mt][1] = ldu32(ylo + r1 * KP + kq);
        }
        #pragma unroll
        for (int n0 = 0; n0 < NT; n0++) {
            int cr = ((NBASE + n0) * 8 + g) * KP + kk + q * 2;
            uint32_t bh0 = ldu32(whi + cr);
            uint32_t bl0 = ldu32(wlo + cr);
            #pragma unroll
            for (int mt = 0; mt < 2; mt++) {
                MMA8(acc[mt][n0], ahi[mt][0], ahi[mt][1], bh0);
                MMA8(acc[mt][n0], alo[mt][0], alo[mt][1], bh0);
                MMA8(acc[mt][n0], ahi[mt][0], ahi[mt][1], bl0);
            }
        }
    }

    // epilogue: a1 cols<128 -> gmem, b1 cols 128..131 -> hsm
    #pragma unroll
    for (int mt = 0; mt < 2; mt++) {
        #pragma unroll
        for (int n0 = 0; n0 < NT; n0++) {
            int col = (NBASE + n0) * 8 + 2 * q;
            int rl0 = rb + mt * 16 + g;
            int rl1 = rl0 + 8;
            float v0 = acc[mt][n0][0], v1 = acc[mt][n0][1];
            float v2 = acc[mt][n0][2], v3 = acc[mt][n0][3];
            if (col < FDIM) {
                long long gr0 = row0 + rl0;
                long long gr1 = row0 + rl1;
                if (gr0 < n) *(float2*)(out_a + gr0 * FDIM + col) = make_float2(v0, v1);
                if (gr1 < n) *(float2*)(out_a + gr1 * FDIM + col) = make_float2(v2, v3);
            } else if (col < FDIM + 4) {
                int cc = col - FDIM;
                hsm[rl0 * 4 + cc]     = v0;
                hsm[rl0 * 4 + cc + 1] = v1;
                hsm[rl1 * 4 + cc]     = v2;
                hsm[rl1 * 4 + cc + 1] = v3;
            }
        }
    }
}

__device__ __forceinline__ void prefetch_tile(
    const float* __restrict__ x, const float* __restrict__ chi,
    long long row0, int n, int tid, float4* xr, float4& cv)
{
    #pragma unroll
    for (int i = 0; i < 8; i++) {
        int linear = i * THREADS + tid;
        int r = linear >> 5;
        int c = (linear & 31) * 4;
        long long gr = row0 + r;
        xr[i] = (gr < n) ? *(const float4*)(x + gr * FDIM + c)
                         : make_float4(0.f, 0.f, 0.f, 0.f);
    }
    int r = tid >> 2, c = tid & 3;
    long long gr = row0 + r;
    cv = (gr < n) ? *(const float4*)(chi + gr * MTOT + c * 4)
                  : make_float4(0.f, 0.f, 0.f, 0.f);
}

__device__ __forceinline__ void fill_tile(
    __half* __restrict__ yh, __half* __restrict__ yl,
    const float4* xr, float4 cv, int tid)
{
    // x -> hi/lo planes
    #pragma unroll
    for (int i = 0; i < 8; i++) {
        int linear = i * THREADS + tid;
        int r = linear >> 5;
        int c = (linear & 31) * 4;
        float4 v = xr[i];
        __half h0 = __float2half_rn(v.x), h1 = __float2half_rn(v.y);
        __half h2 = __float2half_rn(v.z), h3 = __float2half_rn(v.w);
        __half l0 = __float2half_rn(v.x - __half2float(h0));
        __half l1 = __float2half_rn(v.y - __half2float(h1));
        __half l2 = __float2half_rn(v.z - __half2float(h2));
        __half l3 = __float2half_rn(v.w - __half2float(h3));
        uint2 ph = make_uint2(pack2(h0, h1), pack2(h2, h3));
        uint2 pl = make_uint2(pack2(l0, l1), pack2(l2, l3));
        *(uint2*)(yh + r * KP + c) = ph;
        *(uint2*)(yl + r * KP + c) = pl;
    }
    // d_chi (segment sum of squares) via 4-lane butterfly
    {
        int r = tid >> 2, c = tid & 3;
        float4 v = cv;
        float x0 = v.x * v.x, x1 = v.y * v.y, x2 = v.z * v.z, x3 = v.w * v.w;
        float rest = x1 + x2 + x3;
        float t4 = x0 + rest;
        float z0 = (c == 0) ? x0 : 0.f;
        float z1 = (c == 0) ? rest : 0.f;
        float z2 = (c == 1) ? t4 : ((c == 2) ? x0 : 0.f);
        float z3 = (c == 3) ? t4 : ((c == 2) ? rest : 0.f);
        #pragma unroll
        for (int m = 1; m <= 2; m <<= 1) {
            z0 += __shfl_xor_sync(0xffffffffu, z0, m);
            z1 += __shfl_xor_sync(0xffffffffu, z1, m);
            z2 += __shfl_xor_sync(0xffffffffu, z2, m);
            z3 += __shfl_xor_sync(0xffffffffu, z3, m);
        }
        float sv = (c == 0) ? z0 : (c == 1) ? z1 : (c == 2) ? z2 : z3;
        __half h = __float2half_rn(sv);
        __half l = __float2half_rn(sv - __half2float(h));
        __half z = __float2half(0.f);
        yh[r * KP + 128 + c] = h;  yh[r * KP + 132 + c] = z;
        yl[r * KP + 128 + c] = l;  yl[r * KP + 132 + c] = z;
    }
}

__global__ __launch_bounds__(THREADS, 1)
void ib_kernel(const float* __restrict__ x,
               const float* __restrict__ chi,
               const float* __restrict__ W,
               const float* __restrict__ b,
               float* __restrict__ out_a,
               float* __restrict__ out_chi,
               int n, int ntiles)
{
    extern __shared__ char smraw[];
    __half* whi = (__half*)(smraw + WHI_OFF);   // [N=136][K=136] (W transposed)
    __half* wlo = (__half*)(smraw + WLO_OFF);
    float*  hsm = (float*) (smraw + HSM_OFF);   // [ROWS][4]
    float*  bsm = (float*) (smraw + BSM_OFF);   // [KP]

    const int tid  = threadIdx.x;
    const int warp = tid >> 5;
    const int lane = tid & 31;
    const int g  = lane >> 2;
    const int q  = lane & 3;
    const int rw = warp & 3;      // row group 0..3
    const int wn = warp >> 2;     // n group   0..3
    const int rb = rw * 32;

    // ---- W load + split (transposed), zero-padded ----
    for (int i = tid; i < KP * KP; i += THREADS) {
        whi[i] = __float2half(0.f); wlo[i] = __float2half(0.f);
    }
    __syncthreads();
    for (int i = tid; i < KDIM * KDIM; i += THREADS) {
        int k = i / KDIM, j = i % KDIM;
        float v = W[i];
        __half h = __float2half_rn(v);
        __half l = __float2half_rn(v - __half2float(h));
        whi[j * KP + k] = h;
        wlo[j * KP + k] = l;
    }
    if (tid < KP) bsm[tid] = (tid < KDIM) ? b[tid] : 0.0f;
    __syncthreads();

    const int step = gridDim.x;
    int t = blockIdx.x;
    if (t >= ntiles) return;

    float4 xr[8];
    float4 chi_cur, chi_nxt;

    // prologue
    prefetch_tile(x, chi, (long long)t * ROWS, n, tid, xr, chi_nxt);
    {
        __half* yh = (__half*)(smraw + Y_OFF);
        __half* yl = yh + ROWS * KP;
        fill_tile(yh, yl, xr, chi_nxt, tid);
    }
    chi_cur = chi_nxt;
    __syncthreads();

    int cur = 0;
    for (; t < ntiles; t += step) {
        const long long row0 = (long long)t * ROWS;
        const int tn = t + step;
        const bool hn = (tn < ntiles);

        if (hn) prefetch_tile(x, chi, (long long)tn * ROWS, n, tid, xr, chi_nxt);

        __half* yh = (__half*)(smraw + Y_OFF + cur * YBUF_BYTES);
        __half* yl = yh + ROWS * KP;

        if      (wn == 0) tile_compute<4, 0 >(yh, yl, whi, wlo, bsm, hsm, out_a, row0, n, rb, g, q);
        else if (wn == 1) tile_compute<4, 4 >(yh, yl, whi, wlo, bsm, hsm, out_a, row0, n, rb, g, q);
        else if (wn == 2) tile_compute<4, 8 >(yh, yl, whi, wlo, bsm, hsm, out_a, row0, n, rb, g, q);
        else              tile_compute<5, 12>(yh, yl, whi, wlo, bsm, hsm, out_a, row0, n, rb, g, q);
        __syncthreads();

        // chi_out = b1[:, seg] * chi  (chi held in registers)
        {
            int r = tid >> 2, c = tid & 3;
            long long gr = row0 + r;
            if (gr < n) {
                int ia = (c == 0) ? 0 : (c == 1) ? 2 : (c == 2) ? 2 : 3;
                int ib = (c == 0) ? 1 : (c == 1) ? 2 : (c == 2) ? 3 : 3;
                float ha = hsm[r * 4 + ia];
                float hb = hsm[r * 4 + ib];
                float4 v = chi_cur;
                float4 o = make_float4(ha * v.x, hb * v.y, hb * v.z, hb * v.w);
                *(float4*)(out_chi + gr * MTOT + c * 4) = o;
            }
        }

        if (hn) {
            __half* nyh = (__half*)(smraw + Y_OFF + (cur ^ 1) * YBUF_BYTES);
            __half* nyl = nyh + ROWS * KP;
            fill_tile(nyh, nyl, xr, chi_nxt, tid);
        }
        chi_cur = chi_nxt;
        __syncthreads();
        cur ^= 1;
    }
}

extern "C" void kernel_launch(void* const* d_in, const int* in_sizes, int n_in,
                              void* d_out, int out_size)
{
    const float* x   = (const float*)d_in[0];
    const float* chi = (const float*)d_in[1];
    // d_in[2] = point_mask (all-ones; unused by reference math)
    const float* W   = (const float*)d_in[3];
    const float* b   = (const float*)d_in[4];

    int n = in_sizes[0] / FDIM;
    float* out_a   = (float*)d_out;
    float* out_chi = out_a + (size_t)n * FDIM;

    int ntiles = (n + ROWS - 1) / ROWS;

    int dev = 0;
    cudaGetDevice(&dev);
    int smcount = 148;
    cudaDeviceGetAttribute(&smcount, cudaDevAttrMultiProcessorCount, dev);

    cudaFuncSetAttribute(ib_kernel, cudaFuncAttributeMaxDynamicSharedMemorySize,
                         SMEM_BYTES);

    int grid = ntiles < smcount ? ntiles : smcount;
    ib_kernel<<<grid, THREADS, SMEM_BYTES>>>(x, chi, W, b, out_a, out_chi, n, ntiles);
}

// round 5
// speedup vs baseline: 1.9174x; 1.0131x over previous
#include <cuda_runtime.h>
#include <cuda_fp16.h>
#include <cstdint>

#define FDIM   128
#define MTOT   16
#define KDIM   132
#define KP     136
#define ROWS   128
#define THREADS 512

// smem byte offsets
#define WHI_OFF 0
#define WLO_OFF 36992                      // KP*KP*2
#define Y_OFF   73984
#define YBUF    69632                      // hi+lo planes per buffer (2*ROWS*KP*2)
#define HSM_OFF (Y_OFF + 2*YBUF)           // 213248
#define BSM_OFF (HSM_OFF + ROWS*4*4)       // 215296
#define SMEM_BYTES (BSM_OFF + KP*4)        // 215840

__device__ __forceinline__ uint32_t pack2(__half a, __half b) {
    __half2 h = __halves2half2(a, b);
    return *reinterpret_cast<uint32_t*>(&h);
}

#define LDSM_X4(R, A)                                                          \
    asm volatile("ldmatrix.sync.aligned.m8n8.x4.shared.b16 {%0,%1,%2,%3}, [%4];" \
        : "=r"((R)[0]), "=r"((R)[1]), "=r"((R)[2]), "=r"((R)[3]) : "r"(A))
#define LDSM_X2(R, A)                                                          \
    asm volatile("ldmatrix.sync.aligned.m8n8.x2.shared.b16 {%0,%1}, [%2];"     \
        : "=r"((R)[0]), "=r"((R)[1]) : "r"(A))

#define MMA16(C, A, B0, B1)                                                    \
    asm volatile(                                                              \
        "mma.sync.aligned.m16n8k16.row.col.f32.f16.f16.f32 "                   \
        "{%0,%1,%2,%3},{%4,%5,%6,%7},{%8,%9},{%0,%1,%2,%3};"                   \
        : "+f"((C)[0]), "+f"((C)[1]), "+f"((C)[2]), "+f"((C)[3])               \
        : "r"((A)[0]), "r"((A)[1]), "r"((A)[2]), "r"((A)[3]), "r"(B0), "r"(B1))

#define MMA8(C, A0, A1, B0)                                                    \
    asm volatile(                                                              \
        "mma.sync.aligned.m16n8k8.row.col.f32.f16.f16.f32 "                    \
        "{%0,%1,%2,%3},{%4,%5},{%6},{%0,%1,%2,%3};"                            \
        : "+f"((C)[0]), "+f"((C)[1]), "+f"((C)[2]), "+f"((C)[3])               \
        : "r"((A0)), "r"((A1)), "r"(B0))

// One warp: rows [rb, rb+32) x n-tiles [NBASE, NBASE+NT). All fragment loads via ldmatrix.
template<int NT, int NBASE>
__device__ __forceinline__ void tile_compute(
    uint32_t yh, uint32_t yl, uint32_t wh, uint32_t wl,
    const float* __restrict__ bsm, float* __restrict__ hsm,
    float* __restrict__ out_a, long long row0, int n,
    int rb, int lane)
{
    const int g = lane >> 2;
    const int q = lane & 3;
    constexpr int PAIRS = NT / 2;
    constexpr int ODD = NT & 1;

    // lane-dependent ldmatrix base addresses
    const uint32_t aoff = (uint32_t)(((rb + (lane & 15)) * KP + ((lane & 16) ? 8 : 0)) * 2);
    uint32_t abase[2][2];
    abase[0][0] = yh + aoff;  abase[0][1] = yh + aoff + 16 * KP * 2;
    abase[1][0] = yl + aoff;  abase[1][1] = yl + aoff + 16 * KP * 2;

    uint32_t bb[2][PAIRS + ODD];
    #pragma unroll
    for (int p = 0; p < PAIRS; p++) {
        int tilei = NBASE + 2 * p + ((lane & 16) ? 1 : 0);
        uint32_t off = (uint32_t)(((tilei * 8 + (lane & 7)) * KP + ((lane & 8) ? 8 : 0)) * 2);
        bb[0][p] = wh + off;  bb[1][p] = wl + off;
    }
    if (ODD) {
        int tilei = NBASE + NT - 1;
        uint32_t off = (uint32_t)(((tilei * 8 + (lane & 7)) * KP + ((lane & 8) ? 8 : 0)) * 2);
        bb[0][PAIRS] = wh + off;  bb[1][PAIRS] = wl + off;
    }

    float acc[2][NT][4];
    #pragma unroll
    for (int n0 = 0; n0 < NT; n0++) {
        int col = (NBASE + n0) * 8 + 2 * q;
        float b0 = bsm[col], b1 = bsm[col + 1];
        #pragma unroll
        for (int mt = 0; mt < 2; mt++) {
            acc[mt][n0][0] = b0; acc[mt][n0][1] = b1;
            acc[mt][n0][2] = b0; acc[mt][n0][3] = b1;
        }
    }

    // ---- 8 full k16 steps ----
    #pragma unroll 1
    for (int k0 = 0; k0 < 8; k0++) {
        const uint32_t kb = (uint32_t)k0 * 32;   // 16 halves
        uint32_t ah[2][4], al[2][4];
        LDSM_X4(ah[0], abase[0][0] + kb);
        LDSM_X4(ah[1], abase[0][1] + kb);
        LDSM_X4(al[0], abase[1][0] + kb);
        LDSM_X4(al[1], abase[1][1] + kb);
        #pragma unroll
        for (int p = 0; p < PAIRS; p++) {
            uint32_t bh[4], bl[4];
            LDSM_X4(bh, bb[0][p] + kb);
            LDSM_X4(bl, bb[1][p] + kb);
            #pragma unroll
            for (int mt = 0; mt < 2; mt++) {
                MMA16(acc[mt][2*p],     ah[mt], bh[0], bh[1]);
                MMA16(acc[mt][2*p],     al[mt], bh[0], bh[1]);
                MMA16(acc[mt][2*p],     ah[mt], bl[0], bl[1]);
                MMA16(acc[mt][2*p + 1], ah[mt], bh[2], bh[3]);
                MMA16(acc[mt][2*p + 1], al[mt], bh[2], bh[3]);
                MMA16(acc[mt][2*p + 1], ah[mt], bl[2], bl[3]);
            }
        }
        if (ODD) {
            uint32_t bh[2], bl[2];
            LDSM_X2(bh, bb[0][PAIRS] + kb);
            LDSM_X2(bl, bb[1][PAIRS] + kb);
            #pragma unroll
            for (int mt = 0; mt < 2; mt++) {
                MMA16(acc[mt][NT - 1], ah[mt], bh[0], bh[1]);
                MMA16(acc[mt][NT - 1], al[mt], bh[0], bh[1]);
                MMA16(acc[mt][NT - 1], ah[mt], bl[0], bl[1]);
            }
        }
    }

    // ---- tail k8 (k=128..135; 132..135 zero) ----
    {
        const uint32_t kb = 256;
        uint32_t a2h[2][2], a2l[2][2];
        LDSM_X2(a2h[0], abase[0][0] + kb);
        LDSM_X2(a2h[1], abase[0][1] + kb);
        LDSM_X2(a2l[0], abase[1][0] + kb);
        LDSM_X2(a2l[1], abase[1][1] + kb);
        #pragma unroll
        for (int p = 0; p < PAIRS; p++) {
            uint32_t bh[4], bl[4];     // regs 1,3 are garbage (k>=136), unused
            LDSM_X4(bh, bb[0][p] + kb);
            LDSM_X4(bl, bb[1][p] + kb);
            #pragma unroll
            for (int mt = 0; mt < 2; mt++) {
                MMA8(acc[mt][2*p],     a2h[mt][0], a2h[mt][1], bh[0]);
                MMA8(acc[mt][2*p],     a2l[mt][0], a2l[mt][1], bh[0]);
                MMA8(acc[mt][2*p],     a2h[mt][0], a2h[mt][1], bl[0]);
                MMA8(acc[mt][2*p + 1], a2h[mt][0], a2h[mt][1], bh[2]);
                MMA8(acc[mt][2*p + 1], a2l[mt][0], a2l[mt][1], bh[2]);
                MMA8(acc[mt][2*p + 1], a2h[mt][0], a2h[mt][1], bl[2]);
            }
        }
        if (ODD) {
            uint32_t bh[2], bl[2];
            LDSM_X2(bh, bb[0][PAIRS] + kb);
            LDSM_X2(bl, bb[1][PAIRS] + kb);
            #pragma unroll
            for (int mt = 0; mt < 2; mt++) {
                MMA8(acc[mt][NT - 1], a2h[mt][0], a2h[mt][1], bh[0]);
                MMA8(acc[mt][NT - 1], a2l[mt][0], a2l[mt][1], bh[0]);
                MMA8(acc[mt][NT - 1], a2h[mt][0], a2h[mt][1], bl[0]);
            }
        }
    }

    // ---- epilogue: a1 cols<128 -> gmem, b1 cols 128..131 -> hsm ----
    #pragma unroll
    for (int mt = 0; mt < 2; mt++) {
        #pragma unroll
        for (int n0 = 0; n0 < NT; n0++) {
            int col = (NBASE + n0) * 8 + 2 * q;
            int rl0 = rb + mt * 16 + g;
            int rl1 = rl0 + 8;
            float v0 = acc[mt][n0][0], v1 = acc[mt][n0][1];
            float v2 = acc[mt][n0][2], v3 = acc[mt][n0][3];
            if (col < FDIM) {
                long long gr0 = row0 + rl0;
                long long gr1 = row0 + rl1;
                if (gr0 < n) *(float2*)(out_a + gr0 * FDIM + col) = make_float2(v0, v1);
                if (gr1 < n) *(float2*)(out_a + gr1 * FDIM + col) = make_float2(v2, v3);
            } else if (col < FDIM + 4) {
                int cc = col - FDIM;
                hsm[rl0 * 4 + cc]     = v0;
                hsm[rl0 * 4 + cc + 1] = v1;
                hsm[rl1 * 4 + cc]     = v2;
                hsm[rl1 * 4 + cc + 1] = v3;
            }
        }
    }
}

__device__ __forceinline__ void prefetch_tile(
    const float* __restrict__ x, const float* __restrict__ chi,
    long long row0, int n, int tid, float4* xr, float4& cv)
{
    #pragma unroll
    for (int i = 0; i < 8; i++) {
        int linear = i * THREADS + tid;
        int r = linear >> 5;
        int c = (linear & 31) * 4;
        long long gr = row0 + r;
        xr[i] = (gr < n) ? *(const float4*)(x + gr * FDIM + c)
                         : make_float4(0.f, 0.f, 0.f, 0.f);
    }
    int r = tid >> 2, c = tid & 3;
    long long gr = row0 + r;
    cv = (gr < n) ? *(const float4*)(chi + gr * MTOT + c * 4)
                  : make_float4(0.f, 0.f, 0.f, 0.f);
}

__device__ __forceinline__ void fill_tile(
    __half* __restrict__ yh, __half* __restrict__ yl,
    const float4* xr, float4 cv, int tid)
{
    #pragma unroll
    for (int i = 0; i < 8; i++) {
        int linear = i * THREADS + tid;
        int r = linear >> 5;
        int c = (linear & 31) * 4;
        float4 v = xr[i];
        __half h0 = __float2half_rn(v.x), h1 = __float2half_rn(v.y);
        __half h2 = __float2half_rn(v.z), h3 = __float2half_rn(v.w);
        __half l0 = __float2half_rn(v.x - __half2float(h0));
        __half l1 = __float2half_rn(v.y - __half2float(h1));
        __half l2 = __float2half_rn(v.z - __half2float(h2));
        __half l3 = __float2half_rn(v.w - __half2float(h3));
        *(uint2*)(yh + r * KP + c) = make_uint2(pack2(h0, h1), pack2(h2, h3));
        *(uint2*)(yl + r * KP + c) = make_uint2(pack2(l0, l1), pack2(l2, l3));
    }
    {
        int r = tid >> 2, c = tid & 3;
        float4 v = cv;
        float x0 = v.x * v.x, x1 = v.y * v.y, x2 = v.z * v.z, x3 = v.w * v.w;
        float rest = x1 + x2 + x3;
        float t4 = x0 + rest;
        float z0 = (c == 0) ? x0 : 0.f;
        float z1 = (c == 0) ? rest : 0.f;
        float z2 = (c == 1) ? t4 : ((c == 2) ? x0 : 0.f);
        float z3 = (c == 3) ? t4 : ((c == 2) ? rest : 0.f);
        #pragma unroll
        for (int m = 1; m <= 2; m <<= 1) {
            z0 += __shfl_xor_sync(0xffffffffu, z0, m);
            z1 += __shfl_xor_sync(0xffffffffu, z1, m);
            z2 += __shfl_xor_sync(0xffffffffu, z2, m);
            z3 += __shfl_xor_sync(0xffffffffu, z3, m);
        }
        float sv = (c == 0) ? z0 : (c == 1) ? z1 : (c == 2) ? z2 : z3;
        __half h = __float2half_rn(sv);
        __half l = __float2half_rn(sv - __half2float(h));
        __half z = __float2half(0.f);
        yh[r * KP + 128 + c] = h;  yh[r * KP + 132 + c] = z;
        yl[r * KP + 128 + c] = l;  yl[r * KP + 132 + c] = z;
    }
}

__global__ __launch_bounds__(THREADS, 1)
void ib_kernel(const float* __restrict__ x,
               const float* __restrict__ chi,
               const float* __restrict__ W,
               const float* __restrict__ b,
               float* __restrict__ out_a,
               float* __restrict__ out_chi,
               int n, int ntiles)
{
    extern __shared__ char smraw[];
    const uint32_t smb = (uint32_t)__cvta_generic_to_shared(smraw);
    __half* whi = (__half*)(smraw + WHI_OFF);   // [N=136][K=136] (W transposed)
    __half* wlo = (__half*)(smraw + WLO_OFF);
    float*  hsm = (float*) (smraw + HSM_OFF);   // [ROWS][4]
    float*  bsm = (float*) (smraw + BSM_OFF);   // [KP]

    const int tid  = threadIdx.x;
    const int warp = tid >> 5;
    const int lane = tid & 31;
    const int rw = warp & 3;
    const int wn = warp >> 2;
    const int rb = rw * 32;

    // ---- W load + split (transposed), zero-padded ----
    for (int i = tid; i < KP * KP; i += THREADS) {
        whi[i] = __float2half(0.f); wlo[i] = __float2half(0.f);
    }
    __syncthreads();
    for (int i = tid; i < KDIM * KDIM; i += THREADS) {
        int k = i / KDIM, j = i % KDIM;
        float v = W[i];
        __half h = __float2half_rn(v);
        __half l = __float2half_rn(v - __half2float(h));
        whi[j * KP + k] = h;
        wlo[j * KP + k] = l;
    }
    if (tid < KP) bsm[tid] = (tid < KDIM) ? b[tid] : 0.0f;
    __syncthreads();

    const int step = gridDim.x;
    int t = blockIdx.x;
    if (t >= ntiles) return;

    float4 xr[8];
    float4 chi_cur, chi_nxt;

    prefetch_tile(x, chi, (long long)t * ROWS, n, tid, xr, chi_nxt);
    {
        __half* yh = (__half*)(smraw + Y_OFF);
        __half* yl = yh + ROWS * KP;
        fill_tile(yh, yl, xr, chi_nxt, tid);
    }
    chi_cur = chi_nxt;
    __syncthreads();

    int cur = 0;
    for (; t < ntiles; t += step) {
        const long long row0 = (long long)t * ROWS;
        const int tn = t + step;
        const bool hn = (tn < ntiles);

        if (hn) prefetch_tile(x, chi, (long long)tn * ROWS, n, tid, xr, chi_nxt);

        const uint32_t yha = smb + Y_OFF + cur * YBUF;
        const uint32_t yla = yha + ROWS * KP * 2;
        const uint32_t wha = smb + WHI_OFF;
        const uint32_t wla = smb + WLO_OFF;

        if      (wn == 0) tile_compute<4, 0 >(yha, yla, wha, wla, bsm, hsm, out_a, row0, n, rb, lane);
        else if (wn == 1) tile_compute<4, 4 >(yha, yla, wha, wla, bsm, hsm, out_a, row0, n, rb, lane);
        else if (wn == 2) tile_compute<4, 8 >(yha, yla, wha, wla, bsm, hsm, out_a, row0, n, rb, lane);
        else              tile_compute<5, 12>(yha, yla, wha, wla, bsm, hsm, out_a, row0, n, rb, lane);
        __syncthreads();

        // chi_out = b1[:, seg] * chi  (chi held in registers)
        {
            int r = tid >> 2, c = tid & 3;
            long long gr = row0 + r;
            if (gr < n) {
                int ia = (c == 0) ? 0 : (c == 1) ? 2 : (c == 2) ? 2 : 3;
                int ib = (c == 0) ? 1 : (c == 1) ? 2 : (c == 2) ? 3 : 3;
                float ha = hsm[r * 4 + ia];
                float hb = hsm[r * 4 + ib];
                float4 v = chi_cur;
                float4 o = make_float4(ha * v.x, hb * v.y, hb * v.z, hb * v.w);
                *(float4*)(out_chi + gr * MTOT + c * 4) = o;
            }
        }

        if (hn) {
            __half* nyh = (__half*)(smraw + Y_OFF + (cur ^ 1) * YBUF);
            __half* nyl = nyh + ROWS * KP;
            fill_tile(nyh, nyl, xr, chi_nxt, tid);
        }
        chi_cur = chi_nxt;
        __syncthreads();
        cur ^= 1;
    }
}

extern "C" void kernel_launch(void* const* d_in, const int* in_sizes, int n_in,
                              void* d_out, int out_size)
{
    const float* x   = (const float*)d_in[0];
    const float* chi = (const float*)d_in[1];
    // d_in[2] = point_mask (all-ones; unused by reference math)
    const float* W   = (const float*)d_in[3];
    const float* b   = (const float*)d_in[4];

    int n = in_sizes[0] / FDIM;
    float* out_a   = (float*)d_out;
    float* out_chi = out_a + (size_t)n * FDIM;

    int ntiles = (n + ROWS - 1) / ROWS;

    int dev = 0;
    cudaGetDevice(&dev);
    int smcount = 148;
    cudaDeviceGetAttribute(&smcount, cudaDevAttrMultiProcessorCount, dev);

    cudaFuncSetAttribute(ib_kernel, cudaFuncAttributeMaxDynamicSharedMemorySize,
                         SMEM_BYTES);

    int grid = ntiles < smcount ? ntiles : smcount;
    ib_kernel<<<grid, THREADS, SMEM_BYTES>>>(x, chi, W, b, out_a, out_chi, n, ntiles);
}